// round 1
// baseline (speedup 1.0000x reference)
#include <cuda_runtime.h>
#include <cstddef>

// Problem constants
#define H 256
#define W 256
#define KW 129          // rfft bins along W
#define B_ 16
#define C_ 32
#define O_ 32
#define NIMG_X (B_*C_)  // 512
#define NIMG_W (O_*C_)  // 1024
#define NIMG_Y (B_*O_)  // 512

// ---------------- scratch (static device globals; allocation-free) ----------
// xr: [kw][img][h]   complex, after row FFT of x
// wr: [kw][img][h]   for weights
// xf/wf/yf: bin-major [kh][kw][img]
// yr: [kw][img][h]   after inverse col FFT
__device__ float2 g_xr[(size_t)KW * NIMG_X * H];
__device__ float2 g_wr[(size_t)KW * NIMG_W * H];
__device__ float2 g_xf[(size_t)H * KW * NIMG_X];
__device__ float2 g_wf[(size_t)H * KW * NIMG_W];
__device__ float2 g_yf[(size_t)H * KW * NIMG_Y];
__device__ float2 g_yr[(size_t)KW * NIMG_Y * H];

__device__ __forceinline__ float2 cmulf(float2 a, float2 b) {
    return make_float2(fmaf(a.x, b.x, -a.y * b.y), fmaf(a.x, b.y, a.y * b.x));
}

// Fill 128-entry twiddle table: tw[i] = exp(-2*pi*i*i/256)
__device__ __forceinline__ void fill_tw(float2* tw) {
    for (int i = threadIdx.x; i < 128; i += blockDim.x) {
        float sn, cs;
        sincosf(-6.283185307179586f * (float)i / 256.0f, &sn, &cs);
        tw[i] = make_float2(cs, sn);
    }
}

// Block-cooperative Stockham radix-2 FFT-256.
// 8 rows of 256 complex points in A (ping-pong with B). 256 threads:
// warp w owns row w; each lane does 4 butterflies per stage. Result in A.
template <bool INV>
__device__ __forceinline__ void fft256_block(float2* A, float2* B, const float2* tw) {
    const int tp   = threadIdx.x & 31;
    const int base = (threadIdx.x >> 5) * 256;
    float2* src = A;
    float2* dst = B;
#pragma unroll
    for (int stage = 0; stage < 8; stage++) {
        const int s = 1 << stage;
        __syncthreads();
#pragma unroll
        for (int k = 0; k < 4; k++) {
            const int t = tp + k * 32;
            const int j = t & ~(s - 1);      // p << stage, index into tw
            float2 w = tw[j];
            if (INV) w.y = -w.y;
            float2 u = src[base + t];
            float2 v = src[base + t + 128];
            float2 sum = make_float2(u.x + v.x, u.y + v.y);
            float2 dif = make_float2(u.x - v.x, u.y - v.y);
            const int w0 = base + t + j;
            dst[w0]     = sum;
            dst[w0 + s] = cmulf(dif, w);
        }
        float2* tmp = src; src = dst; dst = tmp;
    }
    __syncthreads();   // 8 swaps -> result back in A
}

// ---------------- K1: row FFT (real input), store kw 0..128 transposed ------
// in : [img][h][w] float
// out: [kw][nimg][h] complex
__global__ void k_rowfft(const float* __restrict__ in, float2* __restrict__ out, int nimg) {
    __shared__ float2 A[2048], Bs[2048], tw[128];
    const int bi  = blockIdx.x;
    const int img = bi >> 5;            // 32 tiles of 8 rows per image
    const int h0  = (bi & 31) << 3;
    fill_tw(tw);
    const float* src = in + ((size_t)img * H + h0) * W;
    for (int i = threadIdx.x; i < 2048; i += 256)
        A[i] = make_float2(src[i], 0.0f);
    fft256_block<false>(A, Bs, tw);
    const int r  = threadIdx.x & 7;     // h within tile
    const int ks = threadIdx.x >> 3;
    const size_t obase = (size_t)img * H + h0 + r;
    for (int kw = ks; kw < KW; kw += 32)
        out[(size_t)kw * nimg * H + obase] = A[r * 256 + kw];
}

// ---------------- K2: column FFT (along h), write bin-major -----------------
// in : [kw][nimg][h]
// out: [kh][KW][nimg]
__global__ void k_colfft(const float2* __restrict__ in, float2* __restrict__ out, int nimg) {
    __shared__ float2 A[2048], Bs[2048], tw[128];
    const int kw = blockIdx.x;
    const int i0 = blockIdx.y << 3;     // 8 images per block
    fill_tw(tw);
    const float2* src = in + ((size_t)kw * nimg + i0) * H;
    for (int i = threadIdx.x; i < 2048; i += 256)
        A[i] = src[i];                  // row = local img, point = h
    fft256_block<false>(A, Bs, tw);
    const int r  = threadIdx.x & 7;     // local img
    const int ks = threadIdx.x >> 3;
    for (int kh = ks; kh < 256; kh += 32)
        out[((size_t)kh * KW + kw) * nimg + i0 + r] = A[r * 256 + kh];
}

// ---------------- K3: per-bin channel contraction (complex GEMM) ------------
// xf: [kh][KW][512] (b*32+c), wf: [kh][KW][1024] (o*32+c) -> yf: [kh][KW][512] (b*32+o)
__global__ void k_bingemm(const float2* __restrict__ xf, const float2* __restrict__ wf,
                          float2* __restrict__ yf) {
    __shared__ float2 sx[512];
    __shared__ float2 sw[32 * 33];      // transposed [c][o], padded stride 33
    const size_t bin = (size_t)blockIdx.y * KW + blockIdx.x;   // kh*KW + kw
    const float2* xb = xf + bin * NIMG_X;
    const float2* wb = wf + bin * NIMG_W;
    for (int i = threadIdx.x; i < 512; i += 256) sx[i] = xb[i];
    for (int i = threadIdx.x; i < 1024; i += 256) {
        const int o = i >> 5, c = i & 31;
        sw[c * 33 + o] = wb[i];
    }
    __syncthreads();
    float2* yb = yf + bin * NIMG_Y;
#pragma unroll
    for (int e = 0; e < 2; e++) {
        const int idx = threadIdx.x + e * 256;
        const int b = idx >> 5, o = idx & 31;
        float accx = 0.0f, accy = 0.0f;
#pragma unroll
        for (int c = 0; c < 32; c++) {
            const float2 xv = sx[b * 32 + c];     // broadcast within warp
            const float2 wv = sw[c * 33 + o];     // conflict-free
            accx = fmaf(xv.x, wv.x, accx);
            accx = fmaf(-xv.y, wv.y, accx);
            accy = fmaf(xv.x, wv.y, accy);
            accy = fmaf(xv.y, wv.x, accy);
        }
        yb[idx] = make_float2(accx, accy);
    }
}

// ---------------- K4: inverse column FFT (along kh), scale 1/256 ------------
// in : [kh][KW][nimg] -> out: [kw][nimg][h]
__global__ void k_icolfft(const float2* __restrict__ in, float2* __restrict__ out, int nimg) {
    __shared__ float2 A[2048], Bs[2048], tw[128];
    const int kw = blockIdx.x;
    const int i0 = blockIdx.y << 3;
    fill_tw(tw);
    const int r  = threadIdx.x & 7;
    const int ks = threadIdx.x >> 3;
    for (int kh = ks; kh < 256; kh += 32)
        A[r * 256 + kh] = in[((size_t)kh * KW + kw) * nimg + i0 + r];
    fft256_block<true>(A, Bs, tw);
    const float sc = 1.0f / 256.0f;
    for (int i = threadIdx.x; i < 2048; i += 256) {
        const float2 v = A[i];
        out[((size_t)kw * nimg + i0 + (i >> 8)) * H + (i & 255)] =
            make_float2(v.x * sc, v.y * sc);
    }
}

// ---------------- K5: inverse row FFT (c2r via Hermitian extension) ---------
// in : [kw][nimg][h] -> out: [img][h][w] real, scale 1/256
__global__ void k_irowfft(const float2* __restrict__ in, float* __restrict__ out, int nimg) {
    __shared__ float2 A[2048], Bs[2048], tw[128];
    const int bi  = blockIdx.x;
    const int img = bi >> 5;
    const int h0  = (bi & 31) << 3;
    fill_tw(tw);
    const int r  = threadIdx.x & 7;
    const int ks = threadIdx.x >> 3;
    for (int kw = ks; kw < KW; kw += 32)
        A[r * 256 + kw] = in[((size_t)kw * nimg + img) * H + h0 + r];
    __syncthreads();
    // Hermitian extension: A[kw] = conj(A[256-kw]) for kw in 129..255
    for (int i = threadIdx.x; i < 8 * 127; i += 256) {
        const int rr = i / 127;
        const int kw = 129 + (i - rr * 127);
        const float2 v = A[rr * 256 + (256 - kw)];
        A[rr * 256 + kw] = make_float2(v.x, -v.y);
    }
    fft256_block<true>(A, Bs, tw);
    const float sc = 1.0f / 256.0f;
    for (int i = threadIdx.x; i < 2048; i += 256)
        out[((size_t)img * H + h0 + (i >> 8)) * W + (i & 255)] = A[i].x * sc;
}

// ---------------------------------------------------------------------------
extern "C" void kernel_launch(void* const* d_in, const int* in_sizes, int n_in,
                              void* d_out, int out_size) {
    (void)in_sizes; (void)n_in; (void)out_size;
    const float* x = (const float*)d_in[0];   // (B,C,H,W)
    const float* w = (const float*)d_in[1];   // (O,C,H,W)
    float* out = (float*)d_out;               // (B,O,H,W)

    float2 *xr, *wr, *xf, *wf, *yf, *yr;
    cudaGetSymbolAddress((void**)&xr, g_xr);
    cudaGetSymbolAddress((void**)&wr, g_wr);
    cudaGetSymbolAddress((void**)&xf, g_xf);
    cudaGetSymbolAddress((void**)&wf, g_wf);
    cudaGetSymbolAddress((void**)&yf, g_yf);
    cudaGetSymbolAddress((void**)&yr, g_yr);

    // Forward row FFTs (real -> complex, kw 0..128)
    k_rowfft<<<NIMG_X * 32, 256>>>(x, xr, NIMG_X);
    k_rowfft<<<NIMG_W * 32, 256>>>(w, wr, NIMG_W);
    // Forward column FFTs -> bin-major
    k_colfft<<<dim3(KW, NIMG_X / 8), 256>>>(xr, xf, NIMG_X);
    k_colfft<<<dim3(KW, NIMG_W / 8), 256>>>(wr, wf, NIMG_W);
    // Per-bin channel contraction
    k_bingemm<<<dim3(KW, H), 256>>>(xf, wf, yf);
    // Inverse column FFT
    k_icolfft<<<dim3(KW, NIMG_Y / 8), 256>>>(yf, yr, NIMG_Y);
    // Inverse row FFT (c2r) -> real output
    k_irowfft<<<NIMG_Y * 32, 256>>>(yr, out, NIMG_Y);
}

// round 2
// speedup vs baseline: 1.5113x; 1.5113x over previous
#include <cuda_runtime.h>
#include <cstddef>

// Problem constants
#define H 256
#define W 256
#define KW 129          // rfft bins along W
#define B_ 16
#define C_ 32
#define O_ 32
#define NIMG_X (B_*C_)  // 512
#define NIMG_W (O_*C_)  // 1024
#define NIMG_Y (B_*O_)  // 512

// ---------------- scratch (static device globals; allocation-free) ----------
__device__ float2 g_xr[(size_t)KW * NIMG_X * H];
__device__ float2 g_wr[(size_t)KW * NIMG_W * H];
__device__ float2 g_xf[(size_t)H * KW * NIMG_X];
__device__ float2 g_wf[(size_t)H * KW * NIMG_W];
__device__ float2 g_yf[(size_t)H * KW * NIMG_Y];
__device__ float2 g_yr[(size_t)KW * NIMG_Y * H];

__device__ __forceinline__ float2 cmulf(float2 a, float2 b) {
    return make_float2(fmaf(a.x, b.x, -a.y * b.y), fmaf(a.x, b.y, a.y * b.x));
}

// ---------------- in-register FFT-16 (Stockham radix-2, 4 stages) -----------
// Twiddles W_16^j = exp(-2*pi*i*j/16), j=0..7, hardcoded constants.
template <bool INV>
__device__ __forceinline__ void fft16r(float2* a) {
    const float TR[8] = { 1.f,  0.9238795325112867f,  0.7071067811865476f,  0.3826834323650898f,
                          0.f, -0.3826834323650898f, -0.7071067811865476f, -0.9238795325112867f };
    const float TI[8] = { 0.f, -0.3826834323650898f, -0.7071067811865476f, -0.9238795325112867f,
                         -1.f, -0.9238795325112867f, -0.7071067811865476f, -0.3826834323650898f };
    float2 b[16];
    float2 *s = a, *d = b;
#pragma unroll
    for (int st = 0; st < 4; st++) {
        const int S = 1 << st;
#pragma unroll
        for (int t = 0; t < 8; t++) {
            const int j = t & ~(S - 1);
            const float wr = TR[j];
            const float wi = INV ? -TI[j] : TI[j];
            float2 u = s[t], v = s[t + 8];
            float2 sum = make_float2(u.x + v.x, u.y + v.y);
            float2 dif = make_float2(u.x - v.x, u.y - v.y);
            d[t + j]     = sum;
            d[t + j + S] = make_float2(fmaf(dif.x, wr, -dif.y * wi),
                                       fmaf(dif.x, wi,  dif.y * wr));
        }
        float2* tmp = s; s = d; d = tmp;
    }
    // 4 swaps -> result back in a
}

// ---------------- FFT-256 on registers: 16 threads x 16 points --------------
// Thread t of a row holds a[q] = x[16*q + t]. After call: a[k1] = X[16*k1 + t].
// S: transpose scratch (per-row region of 272 float2). twd: W_256 table (256).
template <bool INV>
__device__ __forceinline__ void fft256_regs(float2* a, float2* S,
                                            const float2* twd, int row, int t) {
    fft16r<INV>(a);                         // inner FFT over n2
#pragma unroll
    for (int k2 = 0; k2 < 16; k2++) {       // middle twiddle W_256^{t*k2}
        float2 w = twd[t * k2];
        if (INV) w.y = -w.y;
        a[k2] = cmulf(a[k2], w);
    }
    float2* Sr = S + row * 272;             // row-owned -> warp-local sync only
    __syncwarp();
#pragma unroll
    for (int k2 = 0; k2 < 16; k2++) Sr[t * 17 + k2] = a[k2];
    __syncwarp();
#pragma unroll
    for (int n1 = 0; n1 < 16; n1++) a[n1] = Sr[n1 * 17 + t];
    __syncwarp();
    fft16r<INV>(a);                         // outer FFT over n1
}

// ---------------- K1: row FFT (real input) -> [kw][nimg][h], kw 0..128 ------
__global__ void k_rowfft(const float* __restrict__ in, float2* __restrict__ out, int nimg) {
    __shared__ float2 S[4352];
    __shared__ float2 twd[256];
    const int tid = threadIdx.x, row = tid >> 4, t = tid & 15;
    const int img = blockIdx.x >> 4, h0 = (blockIdx.x & 15) << 4;
    { float sn, cs; sincosf(-6.283185307179586f * (float)tid / 256.0f, &sn, &cs);
      twd[tid] = make_float2(cs, sn); }
    const float* src = in + ((size_t)img * H + h0 + row) * W + t;
    float2 a[16];
#pragma unroll
    for (int q = 0; q < 16; q++) a[q] = make_float2(src[q * 16], 0.0f);
    __syncthreads();
    fft256_regs<false>(a, S, twd, row, t);
    __syncthreads();
#pragma unroll
    for (int k1 = 0; k1 < 16; k1++) S[(k1 * 16 + t) * 17 + row] = a[k1];
    __syncthreads();
    const size_t ob = (size_t)img * H + h0;
    for (int i = tid; i < KW * 16; i += 256) {
        const int kw_ = i >> 4, r = i & 15;
        out[(size_t)kw_ * nimg * H + ob + r] = S[kw_ * 17 + r];
    }
}

// ---------------- K2: column FFT -> bin-major [kh][KW][nimg] ----------------
__global__ void k_colfft(const float2* __restrict__ in, float2* __restrict__ out, int nimg) {
    __shared__ float2 S[4352];
    __shared__ float2 twd[256];
    const int tid = threadIdx.x, row = tid >> 4, t = tid & 15;
    const int kw = blockIdx.x, img0 = blockIdx.y << 4;
    { float sn, cs; sincosf(-6.283185307179586f * (float)tid / 256.0f, &sn, &cs);
      twd[tid] = make_float2(cs, sn); }
    const float2* src = in + ((size_t)kw * nimg + img0 + row) * H + t;
    float2 a[16];
#pragma unroll
    for (int q = 0; q < 16; q++) a[q] = src[q * 16];
    __syncthreads();
    fft256_regs<false>(a, S, twd, row, t);
    __syncthreads();
#pragma unroll
    for (int k1 = 0; k1 < 16; k1++) S[(k1 * 16 + t) * 17 + row] = a[k1];
    __syncthreads();
    for (int i = tid; i < 4096; i += 256) {
        const int kh = i >> 4, im = i & 15;
        out[((size_t)kh * KW + kw) * nimg + img0 + im] = S[kh * 17 + im];
    }
}

// ---------------- K3: per-bin channel contraction (complex GEMM) ------------
__global__ void k_bingemm(const float2* __restrict__ xf, const float2* __restrict__ wf,
                          float2* __restrict__ yf) {
    __shared__ float2 sx[512];
    __shared__ float2 sw[32 * 33];
    const size_t bin = (size_t)blockIdx.y * KW + blockIdx.x;
    const float2* xb = xf + bin * NIMG_X;
    const float2* wb = wf + bin * NIMG_W;
    for (int i = threadIdx.x; i < 512; i += 256) sx[i] = xb[i];
    for (int i = threadIdx.x; i < 1024; i += 256) {
        const int o = i >> 5, c = i & 31;
        sw[c * 33 + o] = wb[i];
    }
    __syncthreads();
    float2* yb = yf + bin * NIMG_Y;
#pragma unroll
    for (int e = 0; e < 2; e++) {
        const int idx = threadIdx.x + e * 256;
        const int b = idx >> 5, o = idx & 31;
        float accx = 0.0f, accy = 0.0f;
#pragma unroll
        for (int c = 0; c < 32; c++) {
            const float2 xv = sx[b * 32 + c];
            const float2 wv = sw[c * 33 + o];
            accx = fmaf(xv.x, wv.x, accx);
            accx = fmaf(-xv.y, wv.y, accx);
            accy = fmaf(xv.x, wv.y, accy);
            accy = fmaf(xv.y, wv.x, accy);
        }
        yb[idx] = make_float2(accx, accy);
    }
}

// ---------------- K4: inverse column FFT -> [kw][nimg][h], scale 1/256 ------
__global__ void k_icolfft(const float2* __restrict__ in, float2* __restrict__ out, int nimg) {
    __shared__ float2 S[4352];
    __shared__ float2 twd[256];
    const int tid = threadIdx.x, row = tid >> 4, t = tid & 15;
    const int kw = blockIdx.x, img0 = blockIdx.y << 4;
    { float sn, cs; sincosf(-6.283185307179586f * (float)tid / 256.0f, &sn, &cs);
      twd[tid] = make_float2(cs, sn); }
    for (int i = tid; i < 4096; i += 256) {
        const int kh = i >> 4, im = i & 15;
        S[kh * 17 + im] = in[((size_t)kh * KW + kw) * nimg + img0 + im];
    }
    __syncthreads();
    float2 a[16];
#pragma unroll
    for (int q = 0; q < 16; q++) a[q] = S[(q * 16 + t) * 17 + row];
    __syncthreads();
    fft256_regs<true>(a, S, twd, row, t);
    __syncthreads();
    const float sc = 1.0f / 256.0f;
#pragma unroll
    for (int k1 = 0; k1 < 16; k1++)
        S[row * 256 + k1 * 16 + t] = make_float2(a[k1].x * sc, a[k1].y * sc);
    __syncthreads();
    for (int i = tid; i < 4096; i += 256) {
        const int im = i >> 8, h = i & 255;
        out[((size_t)kw * nimg + img0 + im) * H + h] = S[im * 256 + h];
    }
}

// ---------------- K5: inverse row FFT (c2r, Hermitian extension) ------------
__global__ void k_irowfft(const float2* __restrict__ in, float* __restrict__ out, int nimg) {
    __shared__ float2 S[4352];
    __shared__ float2 twd[256];
    const int tid = threadIdx.x, row = tid >> 4, t = tid & 15;
    const int img = blockIdx.x >> 4, h0 = (blockIdx.x & 15) << 4;
    { float sn, cs; sincosf(-6.283185307179586f * (float)tid / 256.0f, &sn, &cs);
      twd[tid] = make_float2(cs, sn); }
    for (int i = tid; i < KW * 16; i += 256) {
        const int kw_ = i >> 4, r = i & 15;
        S[kw_ * 17 + r] = in[((size_t)kw_ * nimg + img) * H + h0 + r];
    }
    __syncthreads();
    float2 a[16];
#pragma unroll
    for (int q = 0; q < 16; q++) {
        const int n = q * 16 + t;
        if (n <= 128) {
            a[q] = S[n * 17 + row];
        } else {
            const float2 v = S[(256 - n) * 17 + row];
            a[q] = make_float2(v.x, -v.y);     // Hermitian extension
        }
    }
    __syncthreads();
    fft256_regs<true>(a, S, twd, row, t);
    __syncthreads();
    float* Sf = (float*)S;
    const float sc = 1.0f / 256.0f;
#pragma unroll
    for (int k1 = 0; k1 < 16; k1++) Sf[row * 256 + k1 * 16 + t] = a[k1].x * sc;
    __syncthreads();
    const size_t ob = ((size_t)img * H + h0) * W;
    for (int i = tid; i < 4096; i += 256)
        out[ob + (size_t)(i >> 8) * W + (i & 255)] = Sf[i];
}

// ---------------------------------------------------------------------------
extern "C" void kernel_launch(void* const* d_in, const int* in_sizes, int n_in,
                              void* d_out, int out_size) {
    (void)in_sizes; (void)n_in; (void)out_size;
    const float* x = (const float*)d_in[0];   // (B,C,H,W)
    const float* w = (const float*)d_in[1];   // (O,C,H,W)
    float* out = (float*)d_out;               // (B,O,H,W)

    float2 *xr, *wr, *xf, *wf, *yf, *yr;
    cudaGetSymbolAddress((void**)&xr, g_xr);
    cudaGetSymbolAddress((void**)&wr, g_wr);
    cudaGetSymbolAddress((void**)&xf, g_xf);
    cudaGetSymbolAddress((void**)&wf, g_wf);
    cudaGetSymbolAddress((void**)&yf, g_yf);
    cudaGetSymbolAddress((void**)&yr, g_yr);

    // Forward row FFTs (real -> complex, kw 0..128)
    k_rowfft<<<NIMG_X * 16, 256>>>(x, xr, NIMG_X);
    k_rowfft<<<NIMG_W * 16, 256>>>(w, wr, NIMG_W);
    // Forward column FFTs -> bin-major
    k_colfft<<<dim3(KW, NIMG_X / 16), 256>>>(xr, xf, NIMG_X);
    k_colfft<<<dim3(KW, NIMG_W / 16), 256>>>(wr, wf, NIMG_W);
    // Per-bin channel contraction
    k_bingemm<<<dim3(KW, H), 256>>>(xf, wf, yf);
    // Inverse column FFT
    k_icolfft<<<dim3(KW, NIMG_Y / 16), 256>>>(yf, yr, NIMG_Y);
    // Inverse row FFT (c2r) -> real output
    k_irowfft<<<NIMG_Y * 16, 256>>>(yr, out, NIMG_Y);
}

// round 3
// speedup vs baseline: 2.3114x; 1.5294x over previous
#include <cuda_runtime.h>
#include <cuda_fp16.h>
#include <cstddef>

// Problem constants
#define H 256
#define W 256
#define KW 129          // rfft bins along W
#define B_ 16
#define C_ 32
#define O_ 32
#define NIMG_X (B_*C_)  // 512
#define NIMG_W (O_*C_)  // 1024
#define NIMG_Y (B_*O_)  // 512

// ---------------- scratch (static device globals; allocation-free) ----------
// Forward-path intermediates in fp16 (half2 = one complex), inverse path fp32.
__device__ __half2 g_xr[(size_t)KW * NIMG_X * H];
__device__ __half2 g_wr[(size_t)KW * NIMG_W * H];
__device__ __half2 g_xf[(size_t)H * KW * NIMG_X];
__device__ __half2 g_wf[(size_t)H * KW * NIMG_W];
__device__ float2  g_yf[(size_t)H * KW * NIMG_Y];
__device__ float2  g_yr[(size_t)KW * NIMG_Y * H];

__device__ __forceinline__ float2 cmulf(float2 a, float2 b) {
    return make_float2(fmaf(a.x, b.x, -a.y * b.y), fmaf(a.x, b.y, a.y * b.x));
}
__device__ __forceinline__ __half2 f2h(float2 v) { return __floats2half2_rn(v.x, v.y); }
__device__ __forceinline__ float2 h2f(__half2 v) { return __half22float2(v); }

// ---------------- in-register FFT-16 (Stockham radix-2, 4 stages) -----------
template <bool INV>
__device__ __forceinline__ void fft16r(float2* a) {
    const float TR[8] = { 1.f,  0.9238795325112867f,  0.7071067811865476f,  0.3826834323650898f,
                          0.f, -0.3826834323650898f, -0.7071067811865476f, -0.9238795325112867f };
    const float TI[8] = { 0.f, -0.3826834323650898f, -0.7071067811865476f, -0.9238795325112867f,
                         -1.f, -0.9238795325112867f, -0.7071067811865476f, -0.3826834323650898f };
    float2 b[16];
    float2 *s = a, *d = b;
#pragma unroll
    for (int st = 0; st < 4; st++) {
        const int S = 1 << st;
#pragma unroll
        for (int t = 0; t < 8; t++) {
            const int j = t & ~(S - 1);
            const float wr = TR[j];
            const float wi = INV ? -TI[j] : TI[j];
            float2 u = s[t], v = s[t + 8];
            float2 sum = make_float2(u.x + v.x, u.y + v.y);
            float2 dif = make_float2(u.x - v.x, u.y - v.y);
            d[t + j]     = sum;
            d[t + j + S] = make_float2(fmaf(dif.x, wr, -dif.y * wi),
                                       fmaf(dif.x, wi,  dif.y * wr));
        }
        float2* tmp = s; s = d; d = tmp;
    }
}

// ---------------- FFT-256 on registers: 16 threads x 16 points --------------
template <bool INV>
__device__ __forceinline__ void fft256_regs(float2* a, float2* S,
                                            const float2* twd, int row, int t) {
    fft16r<INV>(a);
#pragma unroll
    for (int k2 = 0; k2 < 16; k2++) {
        float2 w = twd[t * k2];
        if (INV) w.y = -w.y;
        a[k2] = cmulf(a[k2], w);
    }
    float2* Sr = S + row * 272;
    __syncwarp();
#pragma unroll
    for (int k2 = 0; k2 < 16; k2++) Sr[t * 17 + k2] = a[k2];
    __syncwarp();
#pragma unroll
    for (int n1 = 0; n1 < 16; n1++) a[n1] = Sr[n1 * 17 + t];
    __syncwarp();
    fft16r<INV>(a);
}

// ---------------- K1: row FFT (real input) -> [kw][nimg][h] (fp16) ----------
__global__ void __launch_bounds__(256) k_rowfft(const float* __restrict__ in,
                                                __half2* __restrict__ out, int nimg) {
    __shared__ float2 S[4352];
    __shared__ float2 twd[256];
    const int tid = threadIdx.x, row = tid >> 4, t = tid & 15;
    const int img = blockIdx.x >> 4, h0 = (blockIdx.x & 15) << 4;
    { float sn, cs; sincosf(-6.283185307179586f * (float)tid / 256.0f, &sn, &cs);
      twd[tid] = make_float2(cs, sn); }
    const float* src = in + ((size_t)img * H + h0 + row) * W + t;
    float2 a[16];
#pragma unroll
    for (int q = 0; q < 16; q++) a[q] = make_float2(src[q * 16], 0.0f);
    __syncthreads();
    fft256_regs<false>(a, S, twd, row, t);
    __syncthreads();
#pragma unroll
    for (int k1 = 0; k1 < 16; k1++) S[(k1 * 16 + t) * 17 + row] = a[k1];
    __syncthreads();
    const size_t ob = (size_t)img * H + h0;
    for (int i = tid; i < KW * 16; i += 256) {
        const int kw_ = i >> 4, r = i & 15;
        out[(size_t)kw_ * nimg * H + ob + r] = f2h(S[kw_ * 17 + r]);
    }
}

// ---------------- K2: column FFT -> bin-major [kh][KW][nimg] (fp16) ---------
__global__ void __launch_bounds__(256) k_colfft(const __half2* __restrict__ in,
                                                __half2* __restrict__ out, int nimg) {
    __shared__ float2 S[4352];
    __shared__ float2 twd[256];
    const int tid = threadIdx.x, row = tid >> 4, t = tid & 15;
    const int kw = blockIdx.x, img0 = blockIdx.y << 4;
    { float sn, cs; sincosf(-6.283185307179586f * (float)tid / 256.0f, &sn, &cs);
      twd[tid] = make_float2(cs, sn); }
    const __half2* src = in + ((size_t)kw * nimg + img0 + row) * H + t;
    float2 a[16];
#pragma unroll
    for (int q = 0; q < 16; q++) a[q] = h2f(src[q * 16]);
    __syncthreads();
    fft256_regs<false>(a, S, twd, row, t);
    __syncthreads();
#pragma unroll
    for (int k1 = 0; k1 < 16; k1++) S[(k1 * 16 + t) * 17 + row] = a[k1];
    __syncthreads();
    for (int i = tid; i < 4096; i += 256) {
        const int kh = i >> 4, im = i & 15;
        out[((size_t)kh * KW + kw) * nimg + img0 + im] = f2h(S[kh * 17 + im]);
    }
}

// ---------------- K3: per-bin channel contraction (complex GEMM) ------------
__global__ void __launch_bounds__(256) k_bingemm(const __half2* __restrict__ xf,
                                                 const __half2* __restrict__ wf,
                                                 float2* __restrict__ yf) {
    __shared__ float2 sx[512];
    __shared__ float2 sw[32 * 33];
    const size_t bin = (size_t)blockIdx.y * KW + blockIdx.x;
    const __half2* xb = xf + bin * NIMG_X;
    const __half2* wb = wf + bin * NIMG_W;
    for (int i = threadIdx.x; i < 512; i += 256) sx[i] = h2f(xb[i]);
    for (int i = threadIdx.x; i < 1024; i += 256) {
        const int o = i >> 5, c = i & 31;
        sw[c * 33 + o] = h2f(wb[i]);
    }
    __syncthreads();
    float2* yb = yf + bin * NIMG_Y;
#pragma unroll
    for (int e = 0; e < 2; e++) {
        const int idx = threadIdx.x + e * 256;
        const int b = idx >> 5, o = idx & 31;
        float accx = 0.0f, accy = 0.0f;
#pragma unroll
        for (int c = 0; c < 32; c++) {
            const float2 xv = sx[b * 32 + c];
            const float2 wv = sw[c * 33 + o];
            accx = fmaf(xv.x, wv.x, accx);
            accx = fmaf(-xv.y, wv.y, accx);
            accy = fmaf(xv.x, wv.y, accy);
            accy = fmaf(xv.y, wv.x, accy);
        }
        yb[idx] = make_float2(accx, accy);
    }
}

// ---------------- K4: inverse column FFT -> [kw][nimg][h], scale 1/256 ------
__global__ void __launch_bounds__(256) k_icolfft(const float2* __restrict__ in,
                                                 float2* __restrict__ out, int nimg) {
    __shared__ float2 S[4352];
    __shared__ float2 twd[256];
    const int tid = threadIdx.x, row = tid >> 4, t = tid & 15;
    const int kw = blockIdx.x, img0 = blockIdx.y << 4;
    { float sn, cs; sincosf(-6.283185307179586f * (float)tid / 256.0f, &sn, &cs);
      twd[tid] = make_float2(cs, sn); }
    for (int i = tid; i < 4096; i += 256) {
        const int kh = i >> 4, im = i & 15;
        S[kh * 17 + im] = in[((size_t)kh * KW + kw) * nimg + img0 + im];
    }
    __syncthreads();
    float2 a[16];
#pragma unroll
    for (int q = 0; q < 16; q++) a[q] = S[(q * 16 + t) * 17 + row];
    __syncthreads();
    fft256_regs<true>(a, S, twd, row, t);
    __syncthreads();
    const float sc = 1.0f / 256.0f;
#pragma unroll
    for (int k1 = 0; k1 < 16; k1++)
        S[row * 256 + k1 * 16 + t] = make_float2(a[k1].x * sc, a[k1].y * sc);
    __syncthreads();
    for (int i = tid; i < 4096; i += 256) {
        const int im = i >> 8, h = i & 255;
        out[((size_t)kw * nimg + img0 + im) * H + h] = S[im * 256 + h];
    }
}

// ---------------- K5: inverse row FFT (c2r, Hermitian extension) ------------
__global__ void __launch_bounds__(256) k_irowfft(const float2* __restrict__ in,
                                                 float* __restrict__ out, int nimg) {
    __shared__ float2 S[4352];
    __shared__ float2 twd[256];
    const int tid = threadIdx.x, row = tid >> 4, t = tid & 15;
    const int img = blockIdx.x >> 4, h0 = (blockIdx.x & 15) << 4;
    { float sn, cs; sincosf(-6.283185307179586f * (float)tid / 256.0f, &sn, &cs);
      twd[tid] = make_float2(cs, sn); }
    for (int i = tid; i < KW * 16; i += 256) {
        const int kw_ = i >> 4, r = i & 15;
        S[kw_ * 17 + r] = in[((size_t)kw_ * nimg + img) * H + h0 + r];
    }
    __syncthreads();
    float2 a[16];
#pragma unroll
    for (int q = 0; q < 16; q++) {
        const int n = q * 16 + t;
        if (n <= 128) {
            a[q] = S[n * 17 + row];
        } else {
            const float2 v = S[(256 - n) * 17 + row];
            a[q] = make_float2(v.x, -v.y);     // Hermitian extension
        }
    }
    __syncthreads();
    fft256_regs<true>(a, S, twd, row, t);
    __syncthreads();
    float* Sf = (float*)S;
    const float sc = 1.0f / 256.0f;
#pragma unroll
    for (int k1 = 0; k1 < 16; k1++) Sf[row * 256 + k1 * 16 + t] = a[k1].x * sc;
    __syncthreads();
    const size_t ob = ((size_t)img * H + h0) * W;
    for (int i = tid; i < 4096; i += 256)
        out[ob + (size_t)(i >> 8) * W + (i & 255)] = Sf[i];
}

// ---------------------------------------------------------------------------
extern "C" void kernel_launch(void* const* d_in, const int* in_sizes, int n_in,
                              void* d_out, int out_size) {
    (void)in_sizes; (void)n_in; (void)out_size;
    const float* x = (const float*)d_in[0];   // (B,C,H,W)
    const float* w = (const float*)d_in[1];   // (O,C,H,W)
    float* out = (float*)d_out;               // (B,O,H,W)

    __half2 *xr, *wr, *xf, *wf;
    float2 *yf, *yr;
    cudaGetSymbolAddress((void**)&xr, g_xr);
    cudaGetSymbolAddress((void**)&wr, g_wr);
    cudaGetSymbolAddress((void**)&xf, g_xf);
    cudaGetSymbolAddress((void**)&wf, g_wf);
    cudaGetSymbolAddress((void**)&yf, g_yf);
    cudaGetSymbolAddress((void**)&yr, g_yr);

    // Forward row FFTs (real -> complex, kw 0..128), fp16 out
    k_rowfft<<<NIMG_X * 16, 256>>>(x, xr, NIMG_X);
    k_rowfft<<<NIMG_W * 16, 256>>>(w, wr, NIMG_W);
    // Forward column FFTs -> bin-major, fp16 out
    k_colfft<<<dim3(KW, NIMG_X / 16), 256>>>(xr, xf, NIMG_X);
    k_colfft<<<dim3(KW, NIMG_W / 16), 256>>>(wr, wf, NIMG_W);
    // Per-bin channel contraction (fp32 accumulate + out)
    k_bingemm<<<dim3(KW, H), 256>>>(xf, wf, yf);
    // Inverse column FFT (fp32)
    k_icolfft<<<dim3(KW, NIMG_Y / 16), 256>>>(yf, yr, NIMG_Y);
    // Inverse row FFT (c2r) -> real output
    k_irowfft<<<NIMG_Y * 16, 256>>>(yr, out, NIMG_Y);
}

// round 4
// speedup vs baseline: 2.6467x; 1.1451x over previous
#include <cuda_runtime.h>
#include <cuda_fp16.h>
#include <cstddef>

// Problem constants
#define H 256
#define W 256
#define KW 129          // rfft bins along W
#define B_ 16
#define C_ 32
#define O_ 32
#define NIMG_X (B_*C_)  // 512
#define NIMG_W (O_*C_)  // 1024
#define NIMG_Y (B_*O_)  // 512

// ---------------- scratch (static device globals; allocation-free) ----------
// All intermediates fp16 (half2 = one complex).
__device__ __half2 g_xr[(size_t)KW * NIMG_X * H];
__device__ __half2 g_wr[(size_t)KW * NIMG_W * H];
__device__ __half2 g_xf[(size_t)H * KW * NIMG_X];
__device__ __half2 g_wf[(size_t)H * KW * NIMG_W];
__device__ __half2 g_yf[(size_t)H * KW * NIMG_Y];
__device__ __half2 g_yr[(size_t)KW * NIMG_Y * H];

__device__ __forceinline__ float2 cmulf(float2 a, float2 b) {
    return make_float2(fmaf(a.x, b.x, -a.y * b.y), fmaf(a.x, b.y, a.y * b.x));
}
__device__ __forceinline__ __half2 f2h(float2 v) { return __floats2half2_rn(v.x, v.y); }
__device__ __forceinline__ float2 h2f(__half2 v) { return __half22float2(v); }

// ---------------- in-register FFT-16 (Stockham radix-2, 4 stages) -----------
template <bool INV>
__device__ __forceinline__ void fft16r(float2* a) {
    const float TR[8] = { 1.f,  0.9238795325112867f,  0.7071067811865476f,  0.3826834323650898f,
                          0.f, -0.3826834323650898f, -0.7071067811865476f, -0.9238795325112867f };
    const float TI[8] = { 0.f, -0.3826834323650898f, -0.7071067811865476f, -0.9238795325112867f,
                         -1.f, -0.9238795325112867f, -0.7071067811865476f, -0.3826834323650898f };
    float2 b[16];
    float2 *s = a, *d = b;
#pragma unroll
    for (int st = 0; st < 4; st++) {
        const int S = 1 << st;
#pragma unroll
        for (int t = 0; t < 8; t++) {
            const int j = t & ~(S - 1);
            const float wr = TR[j];
            const float wi = INV ? -TI[j] : TI[j];
            float2 u = s[t], v = s[t + 8];
            float2 sum = make_float2(u.x + v.x, u.y + v.y);
            float2 dif = make_float2(u.x - v.x, u.y - v.y);
            d[t + j]     = sum;
            d[t + j + S] = make_float2(fmaf(dif.x, wr, -dif.y * wi),
                                       fmaf(dif.x, wi,  dif.y * wr));
        }
        float2* tmp = s; s = d; d = tmp;
    }
}

// ---------------- FFT-256 on registers: 16 threads x 16 points --------------
template <bool INV>
__device__ __forceinline__ void fft256_regs(float2* a, float2* S,
                                            const float2* twd, int row, int t) {
    fft16r<INV>(a);
#pragma unroll
    for (int k2 = 0; k2 < 16; k2++) {
        float2 w = twd[t * k2];
        if (INV) w.y = -w.y;
        a[k2] = cmulf(a[k2], w);
    }
    float2* Sr = S + row * 272;
    __syncwarp();
#pragma unroll
    for (int k2 = 0; k2 < 16; k2++) Sr[t * 17 + k2] = a[k2];
    __syncwarp();
#pragma unroll
    for (int n1 = 0; n1 < 16; n1++) a[n1] = Sr[n1 * 17 + t];
    __syncwarp();
    fft16r<INV>(a);
}

// ---------------- K1: packed row FFT (2 real rows per complex FFT) ----------
// in : [img][h][w] float.  out: [kw][nimg][h] fp16, kw 0..128.
// Block: 16 FFT rows = 32 h-rows of one image. grid = nimg*8.
__global__ void __launch_bounds__(256) k_rowfft(const float* __restrict__ in,
                                                __half2* __restrict__ out, int nimg) {
    __shared__ float2 S[4352];
    __shared__ float2 twd[256];
    const int tid = threadIdx.x, row = tid >> 4, t = tid & 15;
    const int img = blockIdx.x >> 3, h0 = (blockIdx.x & 7) << 5;
    { float sn, cs; sincosf(-6.283185307179586f * (float)tid / 256.0f, &sn, &cs);
      twd[tid] = make_float2(cs, sn); }
    const float* pa = in + ((size_t)img * H + h0 + 2 * row) * W + t;
    const float* pb = pa + W;
    float2 a[16];
#pragma unroll
    for (int q = 0; q < 16; q++) a[q] = make_float2(pa[q * 16], pb[q * 16]);
    __syncthreads();
    fft256_regs<false>(a, S, twd, row, t);
    __syncthreads();
#pragma unroll
    for (int k1 = 0; k1 < 16; k1++) S[(k1 * 16 + t) * 17 + row] = a[k1];  // Z[k] @ S[k*17+row]
    __syncthreads();
    const size_t ob = (size_t)img * H + h0;
    for (int i = tid; i < KW * 32; i += 256) {
        const int kw_ = i >> 5, hh = i & 31, r = hh >> 1;
        const float2 Z  = S[kw_ * 17 + r];
        const float2 Zc = S[((256 - kw_) & 255) * 17 + r];   // Z[N-k] (unconjugated)
        float2 v;
        if ((hh & 1) == 0)  // even row: Xa = (Z + conj(Z[N-k]))/2
            v = make_float2((Z.x + Zc.x) * 0.5f, (Z.y - Zc.y) * 0.5f);
        else                // odd row:  Xb = -i(Z - conj(Z[N-k]))/2
            v = make_float2((Z.y + Zc.y) * 0.5f, (Zc.x - Z.x) * 0.5f);
        out[(size_t)kw_ * nimg * H + ob + hh] = f2h(v);
    }
}

// ---------------- K2: column FFT -> bin-major [kh][KW][nimg] (fp16) ---------
__global__ void __launch_bounds__(256) k_colfft(const __half2* __restrict__ in,
                                                __half2* __restrict__ out, int nimg) {
    __shared__ float2 S[4352];
    __shared__ float2 twd[256];
    const int tid = threadIdx.x, row = tid >> 4, t = tid & 15;
    const int kw = blockIdx.x, img0 = blockIdx.y << 4;
    { float sn, cs; sincosf(-6.283185307179586f * (float)tid / 256.0f, &sn, &cs);
      twd[tid] = make_float2(cs, sn); }
    const __half2* src = in + ((size_t)kw * nimg + img0 + row) * H + t;
    float2 a[16];
#pragma unroll
    for (int q = 0; q < 16; q++) a[q] = h2f(src[q * 16]);
    __syncthreads();
    fft256_regs<false>(a, S, twd, row, t);
    __syncthreads();
#pragma unroll
    for (int k1 = 0; k1 < 16; k1++) S[(k1 * 16 + t) * 17 + row] = a[k1];
    __syncthreads();
    for (int i = tid; i < 4096; i += 256) {
        const int kh = i >> 4, im = i & 15;
        out[((size_t)kh * KW + kw) * nimg + img0 + im] = f2h(S[kh * 17 + im]);
    }
}

// ---------------- K3: per-bin channel contraction (complex GEMM) ------------
__global__ void __launch_bounds__(256) k_bingemm(const __half2* __restrict__ xf,
                                                 const __half2* __restrict__ wf,
                                                 __half2* __restrict__ yf) {
    __shared__ float2 sx[512];
    __shared__ float2 sw[32 * 33];
    const size_t bin = (size_t)blockIdx.y * KW + blockIdx.x;
    const __half2* xb = xf + bin * NIMG_X;
    const __half2* wb = wf + bin * NIMG_W;
    for (int i = threadIdx.x; i < 512; i += 256) sx[i] = h2f(xb[i]);
    for (int i = threadIdx.x; i < 1024; i += 256) {
        const int o = i >> 5, c = i & 31;
        sw[c * 33 + o] = h2f(wb[i]);
    }
    __syncthreads();
    __half2* yb = yf + bin * NIMG_Y;
#pragma unroll
    for (int e = 0; e < 2; e++) {
        const int idx = threadIdx.x + e * 256;
        const int b = idx >> 5, o = idx & 31;
        float accx = 0.0f, accy = 0.0f;
#pragma unroll
        for (int c = 0; c < 32; c++) {
            const float2 xv = sx[b * 32 + c];
            const float2 wv = sw[c * 33 + o];
            accx = fmaf(xv.x, wv.x, accx);
            accx = fmaf(-xv.y, wv.y, accx);
            accy = fmaf(xv.x, wv.y, accy);
            accy = fmaf(xv.y, wv.x, accy);
        }
        yb[idx] = f2h(make_float2(accx, accy));
    }
}

// ---------------- K4: inverse column FFT -> [kw][nimg][h], scale 1/256 ------
__global__ void __launch_bounds__(256) k_icolfft(const __half2* __restrict__ in,
                                                 __half2* __restrict__ out, int nimg) {
    __shared__ float2 S[4352];
    __shared__ float2 twd[256];
    const int tid = threadIdx.x, row = tid >> 4, t = tid & 15;
    const int kw = blockIdx.x, img0 = blockIdx.y << 4;
    { float sn, cs; sincosf(-6.283185307179586f * (float)tid / 256.0f, &sn, &cs);
      twd[tid] = make_float2(cs, sn); }
    for (int i = tid; i < 4096; i += 256) {
        const int kh = i >> 4, im = i & 15;
        S[kh * 17 + im] = h2f(in[((size_t)kh * KW + kw) * nimg + img0 + im]);
    }
    __syncthreads();
    float2 a[16];
#pragma unroll
    for (int q = 0; q < 16; q++) a[q] = S[(q * 16 + t) * 17 + row];
    __syncthreads();
    fft256_regs<true>(a, S, twd, row, t);
    __syncthreads();
    const float sc = 1.0f / 256.0f;
#pragma unroll
    for (int k1 = 0; k1 < 16; k1++)
        S[row * 256 + k1 * 16 + t] = make_float2(a[k1].x * sc, a[k1].y * sc);
    __syncthreads();
    for (int i = tid; i < 4096; i += 256) {
        const int im = i >> 8, h = i & 255;
        out[((size_t)kw * nimg + img0 + im) * H + h] = f2h(S[im * 256 + h]);
    }
}

// ---------------- K5: packed inverse row FFT (2 real rows per iFFT) ---------
// in : [kw][nimg][h] fp16.  out: [img][h][w] float.
// Block: 16 iFFT rows = 32 h-rows of one image. grid = nimg*8.
__global__ void __launch_bounds__(256) k_irowfft(const __half2* __restrict__ in,
                                                 float* __restrict__ out, int nimg) {
    __shared__ float2 S[4352];
    __shared__ float2 twd[256];
    const int tid = threadIdx.x, row = tid >> 4, t = tid & 15;
    const int img = blockIdx.x >> 3, h0 = (blockIdx.x & 7) << 5;
    { float sn, cs; sincosf(-6.283185307179586f * (float)tid / 256.0f, &sn, &cs);
      twd[tid] = make_float2(cs, sn); }
    for (int i = tid; i < KW * 32; i += 256) {
        const int kw_ = i >> 5, hh = i & 31;
        S[kw_ * 33 + hh] = h2f(in[(size_t)kw_ * nimg * H + (size_t)img * H + h0 + hh]);
    }
    __syncthreads();
    float2 a[16];
#pragma unroll
    for (int q = 0; q < 16; q++) {
        const int n = q * 16 + t;
        if (n <= 128) {
            const float2 ya = S[n * 33 + 2 * row];
            const float2 yb = S[n * 33 + 2 * row + 1];
            a[q] = make_float2(ya.x - yb.y, ya.y + yb.x);        // Ya + i*Yb
        } else {
            const int m = 256 - n;
            const float2 ya = S[m * 33 + 2 * row];
            const float2 yb = S[m * 33 + 2 * row + 1];
            a[q] = make_float2(ya.x + yb.y, yb.x - ya.y);        // conj(Ya)+i*conj(Yb)
        }
    }
    __syncthreads();
    fft256_regs<true>(a, S, twd, row, t);
    __syncthreads();
    float* Sf = (float*)S;
    const float sc = 1.0f / 256.0f;
#pragma unroll
    for (int k1 = 0; k1 < 16; k1++) {
        const int idx = k1 * 16 + t;
        Sf[(2 * row) * 256 + idx]     = a[k1].x * sc;   // even h-row = real part
        Sf[(2 * row + 1) * 256 + idx] = a[k1].y * sc;   // odd  h-row = imag part
    }
    __syncthreads();
    const size_t ob = ((size_t)img * H + h0) * W;
    for (int i = tid; i < 8192; i += 256)
        out[ob + (size_t)(i >> 8) * W + (i & 255)] = Sf[i];
}

// ---------------------------------------------------------------------------
extern "C" void kernel_launch(void* const* d_in, const int* in_sizes, int n_in,
                              void* d_out, int out_size) {
    (void)in_sizes; (void)n_in; (void)out_size;
    const float* x = (const float*)d_in[0];   // (B,C,H,W)
    const float* w = (const float*)d_in[1];   // (O,C,H,W)
    float* out = (float*)d_out;               // (B,O,H,W)

    __half2 *xr, *wr, *xf, *wf, *yf, *yr;
    cudaGetSymbolAddress((void**)&xr, g_xr);
    cudaGetSymbolAddress((void**)&wr, g_wr);
    cudaGetSymbolAddress((void**)&xf, g_xf);
    cudaGetSymbolAddress((void**)&wf, g_wf);
    cudaGetSymbolAddress((void**)&yf, g_yf);
    cudaGetSymbolAddress((void**)&yr, g_yr);

    // Packed forward row FFTs (2 real rows per complex FFT)
    k_rowfft<<<NIMG_X * 8, 256>>>(x, xr, NIMG_X);
    k_rowfft<<<NIMG_W * 8, 256>>>(w, wr, NIMG_W);
    // Forward column FFTs -> bin-major
    k_colfft<<<dim3(KW, NIMG_X / 16), 256>>>(xr, xf, NIMG_X);
    k_colfft<<<dim3(KW, NIMG_W / 16), 256>>>(wr, wf, NIMG_W);
    // Per-bin channel contraction (fp32 accumulate, fp16 out)
    k_bingemm<<<dim3(KW, H), 256>>>(xf, wf, yf);
    // Inverse column FFT (fp16 in/out)
    k_icolfft<<<dim3(KW, NIMG_Y / 16), 256>>>(yf, yr, NIMG_Y);
    // Packed inverse row FFT -> real output
    k_irowfft<<<NIMG_Y * 8, 256>>>(yr, out, NIMG_Y);
}